// round 1
// baseline (speedup 1.0000x reference)
#include <cuda_runtime.h>
#include <float.h>

// Per-channel min/max over [C, N] fp32. C=1024, N=32768 (derived from sizes).
// One block per channel; float4 streaming loads; warp+smem reduction.

__global__ void __launch_bounds__(256, 8)
channel_minmax_kernel(const float4* __restrict__ in, float* __restrict__ out,
                      int C, int N4) {
    const int c = blockIdx.x;
    const float4* row = in + (size_t)c * N4;

    float mn = FLT_MAX;
    float mx = -FLT_MAX;

    // Grid-stride within row. 8192 float4 / 256 threads = 32 iters.
    // Unroll to batch independent LDG.128s (high MLP).
    int i = threadIdx.x;
    #pragma unroll 8
    for (int it = 0; it < 32; ++it, i += 256) {
        if (i < N4) {
            float4 v = row[i];
            mn = fminf(mn, fminf(fminf(v.x, v.y), fminf(v.z, v.w)));
            mx = fmaxf(mx, fmaxf(fmaxf(v.x, v.y), fmaxf(v.z, v.w)));
        }
    }
    // Tail safety for other shapes (N4 > 8192)
    for (; i < N4; i += 256) {
        float4 v = row[i];
        mn = fminf(mn, fminf(fminf(v.x, v.y), fminf(v.z, v.w)));
        mx = fmaxf(mx, fmaxf(fmaxf(v.x, v.y), fmaxf(v.z, v.w)));
    }

    // Warp butterfly reduction
    #pragma unroll
    for (int o = 16; o > 0; o >>= 1) {
        mn = fminf(mn, __shfl_xor_sync(0xffffffffu, mn, o));
        mx = fmaxf(mx, __shfl_xor_sync(0xffffffffu, mx, o));
    }

    __shared__ float smn[8], smx[8];
    const int wid = threadIdx.x >> 5;
    const int lid = threadIdx.x & 31;
    if (lid == 0) { smn[wid] = mn; smx[wid] = mx; }
    __syncthreads();

    if (wid == 0) {
        mn = (lid < 8) ? smn[lid] : FLT_MAX;
        mx = (lid < 8) ? smx[lid] : -FLT_MAX;
        #pragma unroll
        for (int o = 4; o > 0; o >>= 1) {
            mn = fminf(mn, __shfl_xor_sync(0xffffffffu, mn, o));
            mx = fmaxf(mx, __shfl_xor_sync(0xffffffffu, mx, o));
        }
        if (lid == 0) {
            out[c]     = mn;   // min_vals
            out[C + c] = mx;   // max_vals
        }
    }
}

extern "C" void kernel_launch(void* const* d_in, const int* in_sizes, int n_in,
                              void* d_out, int out_size) {
    const float* in = (const float*)d_in[0];
    float* out = (float*)d_out;

    const int C  = out_size / 2;          // 1024 (min + max per channel)
    const int N  = in_sizes[0] / C;       // 32768
    const int N4 = N / 4;                 // 8192 (N is divisible by 4 here)

    channel_minmax_kernel<<<C, 256>>>((const float4*)in, out, C, N4);
}